// round 6
// baseline (speedup 1.0000x reference)
#include <cuda_runtime.h>
#include <cuda_bf16.h>
#include <cstdio>
#include <cstdint>

#define B_   8
#define NQ_  75
#define NS_  5
#define NG_  4
#define NF_  49
#define C_   64

#define STR_  68
#define NT2_  384
#define AROWS_ 320           // 10 warps x 32 rows (294 valid)
#define BROWS_ 64            // 49 valid

// ---- k2 smem byte offsets ----
#define OFF_AHI   0          // 320*128
#define OFF_ALO   40960
#define OFF_BHI   81920      // 64*128
#define OFF_BLO   90112
#define FBASE_    98304      // float region (offsets in floats below)
#define F_RSQ     0          // 320
#define F_BET     320        // 245
#define F_GAM     565        // 245
#define F_SCR     810        // 245
#define F_SCRQ    1055       // 245
#define F_SCR4    1300       // 980
#define F_SCRQ4   2280       // 980
#define F_RED     3260       // 16
#define SMEM2_TOT (FBASE_ + 3276 * 4)

__device__ float g_p1[B_ * NQ_ * NS_ * NG_];
__device__ float g_p2[B_ * NQ_ * NS_ * NG_];
__device__ float g_kss[B_ * NS_ * NG_ * NF_ * NF_];

__device__ __forceinline__ float multi_gauss(float d2) {
    d2 = fmaxf(d2, 0.0f);
    float t  = __expf(-0.125f * d2);
    float t2 = t * t;
    float t4 = t2 * t2;
    float t8 = t4 * t4;
    float t16 = t8 * t8;
    return t + t2 + t4 + t8 + t16;
}

__device__ __forceinline__ uint32_t smem_u32(const void* p) {
    uint32_t a;
    asm("{ .reg .u64 t; cvta.to.shared.u64 t, %1; cvt.u32.u64 %0, t; }" : "=r"(a) : "l"(p));
    return a;
}
__device__ __forceinline__ uint32_t sw128(uint32_t off) { return off ^ ((off >> 3) & 0x70); }

#define LDM_X4(r0, r1, r2, r3, addr) \
    asm volatile("ldmatrix.sync.aligned.m8n8.x4.shared.b16 {%0,%1,%2,%3}, [%4];" \
                 : "=r"(r0), "=r"(r1), "=r"(r2), "=r"(r3) : "r"(addr))

__device__ __forceinline__ void mma_bf16(float* c, const uint32_t* a, uint32_t b0, uint32_t b1) {
    asm volatile(
        "mma.sync.aligned.m16n8k16.row.col.f32.bf16.bf16.f32 "
        "{%0,%1,%2,%3}, {%4,%5,%6,%7}, {%8,%9}, {%0,%1,%2,%3};"
        : "+f"(c[0]), "+f"(c[1]), "+f"(c[2]), "+f"(c[3])
        : "r"(a[0]), "r"(a[1]), "r"(a[2]), "r"(a[3]), "r"(b0), "r"(b1));
}

__device__ __forceinline__ unsigned long long pack4bf(float x0, float x1, float x2, float x3,
                                                      float& l0, float& l1, float& l2, float& l3) {
    __nv_bfloat16 h0 = __float2bfloat16(x0), h1 = __float2bfloat16(x1);
    __nv_bfloat16 h2 = __float2bfloat16(x2), h3 = __float2bfloat16(x3);
    l0 = x0 - __bfloat162float(h0); l1 = x1 - __bfloat162float(h1);
    l2 = x2 - __bfloat162float(h2); l3 = x3 - __bfloat162float(h3);
    return (unsigned long long)__bfloat16_as_ushort(h0)
        | ((unsigned long long)__bfloat16_as_ushort(h1) << 16)
        | ((unsigned long long)__bfloat16_as_ushort(h2) << 32)
        | ((unsigned long long)__bfloat16_as_ushort(h3) << 48);
}
__device__ __forceinline__ unsigned long long pack4lo(float l0, float l1, float l2, float l3) {
    return (unsigned long long)__bfloat16_as_ushort(__float2bfloat16(l0))
        | ((unsigned long long)__bfloat16_as_ushort(__float2bfloat16(l1)) << 16)
        | ((unsigned long long)__bfloat16_as_ushort(__float2bfloat16(l2)) << 32)
        | ((unsigned long long)__bfloat16_as_ushort(__float2bfloat16(l3)) << 48);
}

// ---------------------------------------------------------------------------
// k1a: per (b,s,g) -> Kss (49x49) -> g_kss (scalar FFMA)
// ---------------------------------------------------------------------------
__global__ __launch_bounds__(64) void k1a_kss(const float* __restrict__ sup) {
    __shared__ float sraw[49 * STR_];
    __shared__ float ssq[52];

    int bid = blockIdx.x;
    int tid = threadIdx.x;

    const float* sb = sup + (size_t)bid * 49 * 64;
    for (int idx = tid; idx < 49 * 16; idx += 64) {
        int r = idx >> 4, c4 = idx & 15;
        *(float4*)(sraw + r * STR_ + c4 * 4) = *(const float4*)(sb + r * 64 + c4 * 4);
    }
    __syncthreads();

    if (tid < 49) {
        const float2* xr = (const float2*)(sraw + tid * STR_);
        float a0 = 0.f, a1 = 0.f;
        #pragma unroll
        for (int c = 0; c < 32; c++) { float2 x = xr[c]; a0 = fmaf(x.x, x.x, a0); a1 = fmaf(x.y, x.y, a1); }
        ssq[tid] = a0 + a1;
    }
    __syncthreads();

    if (tid < 49) {
        int it = tid / 7, jt = tid - it * 7;
        float acc[49];
        #pragma unroll
        for (int k = 0; k < 49; k++) acc[k] = 0.f;
        const float2* A  = (const float2*)(sraw + it * 7 * STR_);
        const float2* Bm = (const float2*)(sraw + jt * 7 * STR_);
        #pragma unroll 1
        for (int c2 = 0; c2 < 32; c2++) {
            float2 a[7], bb[7];
            #pragma unroll
            for (int k = 0; k < 7; k++) a[k]  = A[k * (STR_ / 2) + c2];
            #pragma unroll
            for (int k = 0; k < 7; k++) bb[k] = Bm[k * (STR_ / 2) + c2];
            #pragma unroll
            for (int ii = 0; ii < 7; ii++)
                #pragma unroll
                for (int jj = 0; jj < 7; jj++) {
                    acc[ii * 7 + jj] = fmaf(a[ii].x, bb[jj].x, acc[ii * 7 + jj]);
                    acc[ii * 7 + jj] = fmaf(a[ii].y, bb[jj].y, acc[ii * 7 + jj]);
                }
        }
        float* kout = g_kss + (size_t)bid * 2401;
        #pragma unroll
        for (int ii = 0; ii < 7; ii++) {
            float ri = ssq[it * 7 + ii];
            #pragma unroll
            for (int jj = 0; jj < 7; jj++) {
                float d2 = ri + ssq[jt * 7 + jj] - 2.0f * acc[ii * 7 + jj];
                kout[(it * 7 + ii) * 49 + jt * 7 + jj] = multi_gauss(d2);
            }
        }
    }
}

// ---------------------------------------------------------------------------
// k1b: bilinear beta^T Kss beta (Kss from g_kss, L2-hot)
// ---------------------------------------------------------------------------
__global__ __launch_bounds__(256) void k1b_bilinear(const float* __restrict__ beta) {
    __shared__ float kss[49 * 50];
    __shared__ float betas[15 * 50];
    __shared__ float scr[735];

    int bid = blockIdx.x;
    int g = bid & 3;
    int rest = bid >> 2;
    int s = rest % NS_;  rest /= NS_;
    int vt = rest % 5;
    int b = rest / 5;
    int tid = threadIdx.x;

    int bid160 = (b * NS_ + s) * NG_ + g;
    const float* ksrc = g_kss + (size_t)bid160 * 2401;
    for (int idx = tid; idx < 2401; idx += 256) {
        int i = idx / 49, j = idx - i * 49;
        kss[i * 50 + j] = ksrc[idx];
    }
    for (int idx = tid; idx < 15 * 49; idx += 256) {
        int vv = idx / 49, j = idx - vv * 49;
        int v = vt * 15 + vv;
        size_t off = ((size_t)((b * NQ_ + v) * NS_ + s) * NG_ + g) * 49 + j;
        betas[vv * 50 + j] = beta[off];
    }
    __syncthreads();

    for (int t = tid; t < 735; t += 256) {
        int vv = t / 49, i = t - vv * 49;
        const float2* kr = (const float2*)(kss + i * 50);
        const float2* bv = (const float2*)(betas + vv * 50);
        float r0 = 0.f, r1 = 0.f;
        #pragma unroll
        for (int c = 0; c < 24; c++) {
            float2 kk = kr[c], bb = bv[c];
            r0 = fmaf(kk.x, bb.x, r0);
            r1 = fmaf(kk.y, bb.y, r1);
        }
        float r = r0 + r1 + kss[i * 50 + 48] * betas[vv * 50 + 48];
        scr[t] = betas[vv * 50 + i] * r;
    }
    __syncthreads();

    if (tid < 15) {
        float acc = 0.f;
        #pragma unroll
        for (int k = 0; k < 49; k++) acc += scr[tid * 49 + k];
        int v = vt * 15 + tid;
        g_p1[((b * NQ_ + v) * NS_ + s) * NG_ + g] = acc;
    }
}

// ---------------------------------------------------------------------------
// k2: per (b,v,g). Dots via mma.sync bf16 split precision (HMMA fallback path):
//   D = Ahi*Bhi^T + Ahi*Blo^T + Alo*Bhi^T (fp32 accum in registers).
// A[320x64]: support(245)+query(49)+pad; B[64x64]: query(49)+pad.
// Fused epilogue: d2 -> multi_gauss -> bilinear via smem scratch reduce.
// ---------------------------------------------------------------------------
__global__ __launch_bounds__(NT2_, 1) void k2_main(const float* __restrict__ sup,
                                                   const float* __restrict__ qry,
                                                   const float* __restrict__ beta,
                                                   const float* __restrict__ gamma) {
    extern __shared__ char smc[];
    uint32_t sbase = smem_u32(smc);
    float* fbase = (float*)(smc + FBASE_);
    float* rsq   = fbase + F_RSQ;
    float* bet   = fbase + F_BET;
    float* gam   = fbase + F_GAM;
    float* scr   = fbase + F_SCR;
    float* scrq  = fbase + F_SCRQ;
    float* scr4  = fbase + F_SCR4;
    float* scrq4 = fbase + F_SCRQ4;
    float* red   = fbase + F_RED;

    int bid = blockIdx.x;
    int g = bid & 3;
    int bv = bid >> 2;
    int b = bv / NQ_;
    int tid = threadIdx.x;
    int wid = tid >> 5;
    int lane = tid & 31;

    const float* supb = sup + (size_t)(b * (NS_ * NG_) + g) * 49 * 64;
    const float* qryb = qry + ((size_t)bv * NG_ + g) * 49 * 64;

    if (tid >= 294 && tid < 320) rsq[tid] = 0.f;

    // ---- A tile: 320 rows x 64, hi/lo bf16 + rsq via 16-lane shfl reduce ----
    #pragma unroll 1
    for (int it = 0; it < 14; it++) {
        int idx = tid + it * NT2_;
        float sq = 0.f;
        int r = idx >> 4, c8 = idx & 15;
        if (idx < AROWS_ * 16) {
            unsigned long long hi = 0ull, lo = 0ull;
            if (r < 294) {
                float4 v;
                if (r < 245) {
                    int s = r / 49, i = r - s * 49;
                    v = *(const float4*)(supb + (size_t)s * (NG_ * 49 * 64) + i * 64 + c8 * 4);
                } else {
                    v = *(const float4*)(qryb + (r - 245) * 64 + c8 * 4);
                }
                float l0, l1, l2, l3;
                hi = pack4bf(v.x, v.y, v.z, v.w, l0, l1, l2, l3);
                lo = pack4lo(l0, l1, l2, l3);
                sq = fmaf(v.x, v.x, fmaf(v.y, v.y, fmaf(v.z, v.z, v.w * v.w)));
            }
            uint32_t sw = sw128((uint32_t)(r * 128 + c8 * 8));
            *(unsigned long long*)(smc + OFF_AHI + sw) = hi;
            *(unsigned long long*)(smc + OFF_ALO + sw) = lo;
        }
        #pragma unroll
        for (int o = 1; o < 16; o <<= 1) sq += __shfl_xor_sync(0xffffffffu, sq, o);
        if (idx < AROWS_ * 16 && (idx & 15) == 0 && r < 294) rsq[r] = sq;
    }
    // ---- B tile: 64 rows x 64 (query) ----
    #pragma unroll 1
    for (int it = 0; it < 3; it++) {
        int idx = tid + it * NT2_;
        if (idx < BROWS_ * 16) {
            int r = idx >> 4, c8 = idx & 15;
            unsigned long long hi = 0ull, lo = 0ull;
            if (r < 49) {
                float4 v = *(const float4*)(qryb + r * 64 + c8 * 4);
                float l0, l1, l2, l3;
                hi = pack4bf(v.x, v.y, v.z, v.w, l0, l1, l2, l3);
                lo = pack4lo(l0, l1, l2, l3);
            }
            uint32_t sw = sw128((uint32_t)(r * 128 + c8 * 8));
            *(unsigned long long*)(smc + OFF_BHI + sw) = hi;
            *(unsigned long long*)(smc + OFF_BLO + sw) = lo;
        }
    }
    for (int idx = tid; idx < NS_ * 49; idx += NT2_) {
        int s = idx / 49, j = idx - s * 49;
        size_t off = ((size_t)(bv * NS_ + s) * NG_ + g) * 49 + j;
        bet[idx] = beta[off];
        gam[idx] = gamma[off];
    }
    __syncthreads();

    if (wid < 10) {
        float Cf[2][8][4];
        #pragma unroll
        for (int mt = 0; mt < 2; mt++)
            #pragma unroll
            for (int nt = 0; nt < 8; nt++)
                #pragma unroll
                for (int e = 0; e < 4; e++) Cf[mt][nt][e] = 0.f;

        int a_row = (lane & 15);
        int a_kh  = (lane >> 4);
        int b_row = (lane & 7) + ((lane >> 4) << 3);
        int b_kh  = (lane >> 3) & 1;

        #pragma unroll 1
        for (int k = 0; k < 4; k++) {
            uint32_t ah[2][4], al[2][4], bh[4][4], bl[4][4];
            #pragma unroll
            for (int mt = 0; mt < 2; mt++) {
                uint32_t off = sw128((uint32_t)((wid * 32 + mt * 16 + a_row) * 128 + k * 32 + a_kh * 16));
                LDM_X4(ah[mt][0], ah[mt][1], ah[mt][2], ah[mt][3], sbase + OFF_AHI + off);
                LDM_X4(al[mt][0], al[mt][1], al[mt][2], al[mt][3], sbase + OFF_ALO + off);
            }
            #pragma unroll
            for (int np = 0; np < 4; np++) {
                uint32_t off = sw128((uint32_t)((np * 16 + b_row) * 128 + k * 32 + b_kh * 16));
                LDM_X4(bh[np][0], bh[np][1], bh[np][2], bh[np][3], sbase + OFF_BHI + off);
                LDM_X4(bl[np][0], bl[np][1], bl[np][2], bl[np][3], sbase + OFF_BLO + off);
            }
            #pragma unroll
            for (int mt = 0; mt < 2; mt++)
                #pragma unroll
                for (int nt = 0; nt < 8; nt++) {
                    uint32_t bh0 = bh[nt >> 1][(nt & 1) * 2], bh1 = bh[nt >> 1][(nt & 1) * 2 + 1];
                    uint32_t bl0 = bl[nt >> 1][(nt & 1) * 2], bl1 = bl[nt >> 1][(nt & 1) * 2 + 1];
                    mma_bf16(Cf[mt][nt], ah[mt], bh0, bh1);
                    mma_bf16(Cf[mt][nt], ah[mt], bl0, bl1);
                    mma_bf16(Cf[mt][nt], al[mt], bh0, bh1);
                }
        }

        // ---- fused epilogue from fragments ----
        int p4 = lane & 3;
        #pragma unroll
        for (int mt = 0; mt < 2; mt++)
            #pragma unroll
            for (int hf = 0; hf < 2; hf++) {
                int r = wid * 32 + mt * 16 + (lane >> 2) + hf * 8;
                if (r < 245) {
                    float rr = rsq[r];
                    int s = r / 49;
                    const float* gs = gam + s * 49;
                    float part = 0.f;
                    #pragma unroll
                    for (int nt = 0; nt < 8; nt++)
                        #pragma unroll
                        for (int e = 0; e < 2; e++) {
                            int col = nt * 8 + 2 * p4 + e;
                            if (col < 49) {
                                float d2 = rr + rsq[245 + col] - 2.f * Cf[mt][nt][hf * 2 + e];
                                part = fmaf(multi_gauss(d2), gs[col], part);
                            }
                        }
                    scr4[r * 4 + p4] = part;
                } else if (r < 294) {
                    float rr = rsq[r];
                    int q = r - 245;
                    float pq[5] = {0.f, 0.f, 0.f, 0.f, 0.f};
                    #pragma unroll
                    for (int nt = 0; nt < 8; nt++)
                        #pragma unroll
                        for (int e = 0; e < 2; e++) {
                            int col = nt * 8 + 2 * p4 + e;
                            if (col < 49) {
                                float d2 = rr + rsq[245 + col] - 2.f * Cf[mt][nt][hf * 2 + e];
                                float kv = multi_gauss(d2);
                                #pragma unroll
                                for (int s = 0; s < 5; s++) pq[s] = fmaf(kv, gam[s * 49 + col], pq[s]);
                            }
                        }
                    #pragma unroll
                    for (int s = 0; s < 5; s++) scrq4[(s * 49 + q) * 4 + p4] = pq[s];
                }
            }
    }
    __syncthreads();

    for (int j = tid; j < 490; j += NT2_) {
        if (j < 245) {
            float v = scr4[j * 4] + scr4[j * 4 + 1] + scr4[j * 4 + 2] + scr4[j * 4 + 3];
            scr[j] = bet[j] * v;
        } else {
            int q = j - 245;
            float v = scrq4[q * 4] + scrq4[q * 4 + 1] + scrq4[q * 4 + 2] + scrq4[q * 4 + 3];
            scrq[q] = gam[q] * v;
        }
    }
    __syncthreads();

    if (tid < 10) {
        int s = tid % 5;
        const float* src = (tid < 5) ? (scr + s * 49) : (scrq + s * 49);
        float acc = 0.f;
        #pragma unroll
        for (int k = 0; k < 49; k++) acc += src[k];
        red[tid] = acc;
    }
    __syncthreads();

    if (tid < NS_) {
        int idx = (bv * NS_ + tid) * NG_ + g;
        g_p2[idx] = red[5 + tid] - 2.0f * red[tid];
    }
}

__global__ void k3_reduce(float* __restrict__ out) {
    int o = blockIdx.x * blockDim.x + threadIdx.x;
    if (o < B_ * NQ_ * NS_) {
        float s = 0.0f;
        #pragma unroll
        for (int g = 0; g < NG_; g++) s += g_p1[o * NG_ + g] + g_p2[o * NG_ + g];
        out[o] = 0.25f * s;
    }
}

extern "C" void kernel_launch(void* const* d_in, const int* in_sizes, int n_in,
                              void* d_out, int out_size) {
    const float* sup   = (const float*)d_in[0];
    const float* qry   = (const float*)d_in[1];
    const float* beta  = (const float*)d_in[2];
    const float* gamma = (const float*)d_in[3];
    float* out = (float*)d_out;

    static bool configured = false;
    if (!configured) {
        cudaFuncSetAttribute(k2_main, cudaFuncAttributeMaxDynamicSharedMemorySize, SMEM2_TOT);
        configured = true;
    }

    k1a_kss<<<B_ * NS_ * NG_, 64>>>(sup);
    k1b_bilinear<<<B_ * NS_ * NG_ * 5, 256>>>(beta);
    k2_main<<<B_ * NQ_ * NG_, NT2_, SMEM2_TOT>>>(sup, qry, beta, gamma);
    k3_reduce<<<(B_ * NQ_ * NS_ + 255) / 256, 256>>>(out);
}

// round 7
// speedup vs baseline: 1.0333x; 1.0333x over previous
#include <cuda_runtime.h>
#include <cstdio>
#include <cstdint>

#define B_   8
#define NQ_  75
#define NS_  5
#define NG_  4
#define NF_  49
#define C_   64

#define ROWS_ 294
#define STR_  68
#define NT2_  320

__device__ float g_ps[B_ * NQ_ * NS_ * NG_];            // full per-(b,v,s,g) partial
__device__ float g_kss[B_ * NS_ * NG_ * NF_ * NF_];     // [bid160][i*49+j]

__device__ __forceinline__ float multi_gauss(float d2) {
    d2 = fmaxf(d2, 0.0f);
    float t  = __expf(-0.125f * d2);
    float t2 = t * t;
    float t4 = t2 * t2;
    float t8 = t4 * t4;
    float t16 = t8 * t8;
    return t + t2 + t4 + t8 + t16;
}

// ---------------------------------------------------------------------------
// k1a: per (b,s,g) -> Kss (49x49) -> g_kss (scalar FFMA 7x7 micro-tiles)
// ---------------------------------------------------------------------------
__global__ __launch_bounds__(64) void k1a_kss(const float* __restrict__ sup) {
    __shared__ float sraw[49 * STR_];
    __shared__ float ssq[52];

    int bid = blockIdx.x;              // 0..159 = (b*5+s)*4+g
    int tid = threadIdx.x;

    const float* sb = sup + (size_t)bid * 49 * 64;
    for (int idx = tid; idx < 49 * 16; idx += 64) {
        int r = idx >> 4, c4 = idx & 15;
        *(float4*)(sraw + r * STR_ + c4 * 4) = *(const float4*)(sb + r * 64 + c4 * 4);
    }
    __syncthreads();

    if (tid < 49) {
        const float2* xr = (const float2*)(sraw + tid * STR_);
        float a0 = 0.f, a1 = 0.f;
        #pragma unroll
        for (int c = 0; c < 32; c++) { float2 x = xr[c]; a0 = fmaf(x.x, x.x, a0); a1 = fmaf(x.y, x.y, a1); }
        ssq[tid] = a0 + a1;
    }
    __syncthreads();

    if (tid < 49) {
        int it = tid / 7, jt = tid - it * 7;
        float acc[49];
        #pragma unroll
        for (int k = 0; k < 49; k++) acc[k] = 0.f;
        const float2* A  = (const float2*)(sraw + it * 7 * STR_);
        const float2* Bm = (const float2*)(sraw + jt * 7 * STR_);
        #pragma unroll 1
        for (int c2 = 0; c2 < 32; c2++) {
            float2 a[7], bb[7];
            #pragma unroll
            for (int k = 0; k < 7; k++) a[k]  = A[k * (STR_ / 2) + c2];
            #pragma unroll
            for (int k = 0; k < 7; k++) bb[k] = Bm[k * (STR_ / 2) + c2];
            #pragma unroll
            for (int ii = 0; ii < 7; ii++)
                #pragma unroll
                for (int jj = 0; jj < 7; jj++) {
                    acc[ii * 7 + jj] = fmaf(a[ii].x, bb[jj].x, acc[ii * 7 + jj]);
                    acc[ii * 7 + jj] = fmaf(a[ii].y, bb[jj].y, acc[ii * 7 + jj]);
                }
        }
        float* kout = g_kss + (size_t)bid * 2401;
        #pragma unroll
        for (int ii = 0; ii < 7; ii++) {
            float ri = ssq[it * 7 + ii];
            #pragma unroll
            for (int jj = 0; jj < 7; jj++) {
                float d2 = ri + ssq[jt * 7 + jj] - 2.0f * acc[ii * 7 + jj];
                kout[(it * 7 + ii) * 49 + jt * 7 + jj] = multi_gauss(d2);
            }
        }
    }
}

// ---------------------------------------------------------------------------
// k2: per (b,v,g). Everything fused:
//   - cross + query-query dots via 7x7 scalar-FFMA micro-tiles (2 CTA/SM)
//   - d2 -> multi_gauss -> bilinear (mmd_sq, mmd_q)
//   - beta^T Kss beta streamed from g_kss (L2-hot) -> mmd_s
//   emits g_ps[(bv,s,g)] = mmd_s + mmd_q - 2*mmd_sq
// ---------------------------------------------------------------------------
__global__ __launch_bounds__(NT2_, 2) void k2_main(const float* __restrict__ sup,
                                                   const float* __restrict__ qry,
                                                   const float* __restrict__ beta,
                                                   const float* __restrict__ gamma) {
    extern __shared__ float sm[];
    float* xs   = sm;                     // 294*68
    float* rsq  = xs + ROWS_ * STR_;      // 296
    float* bet  = rsq + 296;              // 245
    float* gam  = bet + 245;              // 245
    float* scr  = gam + 245;              // 245 (mmd_sq partials by tid, s-blocked)
    float* scrq = scr + 245;              // 245 (mmd_q partials [s*49+q])
    float* red  = scrq + 245;             // 24: [0..4]=mmd_sq [5..9]=mmd_q [12..21]=wsum(p1)

    int bid = blockIdx.x;                 // 0..2399
    int g = bid & 3;
    int bv = bid >> 2;
    int b = bv / NQ_;
    int tid = threadIdx.x;

    const float* supb = sup + (size_t)(b * (NS_ * NG_) + g) * 49 * 64;
    const float* qryb = qry + ((size_t)bv * NG_ + g) * 49 * 64;

    // ---- tile load (float4) + rsq via 16-lane shfl reduce ----
    #pragma unroll 1
    for (int pass = 0; pass < 15; pass++) {
        int idx = tid + pass * NT2_;      // NT2_ % 16 == 0 -> 16-lane groups share a row
        float sq = 0.f;
        int r = idx >> 4, c4 = idx & 15;
        bool ok = (idx < ROWS_ * 16);
        if (ok) {
            float4 v;
            if (r < 245) {
                int s = r / 49;
                int i = r - s * 49;
                v = *(const float4*)(supb + (size_t)s * (NG_ * 49 * 64) + i * 64 + c4 * 4);
            } else {
                v = *(const float4*)(qryb + (r - 245) * 64 + c4 * 4);
            }
            *(float4*)(xs + r * STR_ + c4 * 4) = v;
            sq = fmaf(v.x, v.x, fmaf(v.y, v.y, fmaf(v.z, v.z, v.w * v.w)));
        }
        #pragma unroll
        for (int o = 1; o < 16; o <<= 1) sq += __shfl_xor_sync(0xffffffffu, sq, o);
        if (ok && c4 == 0) rsq[r] = sq;
    }
    for (int idx = tid; idx < NS_ * 49; idx += NT2_) {
        int s = idx / 49, j = idx - s * 49;
        size_t off = ((size_t)(bv * NS_ + s) * NG_ + g) * 49 + j;
        bet[idx] = beta[off];
        gam[idx] = gamma[off];
    }
    __syncthreads();

    // ---- mmd_s: stream Kss from g_kss (L2-hot), 64 threads per s ----
    {
        int sg = tid >> 6;                // 0..4
        int l64 = tid & 63;
        const float* ks = g_kss + ((size_t)(b * NS_ + sg) * NG_ + g) * 2401;
        const float* bs = bet + sg * 49;
        float a = 0.f;
        #pragma unroll 2
        for (int e = l64; e < 2401; e += 64) {
            int i = e / 49;
            int j = e - i * 49;
            a += ks[e] * bs[i] * bs[j];
        }
        #pragma unroll
        for (int o = 1; o < 32; o <<= 1) a += __shfl_xor_sync(0xffffffffu, a, o);
        if ((tid & 31) == 0) red[12 + (tid >> 5)] = a;   // wsum per warp; s = warp/2
    }

    // ---- dot micro-tiles + fused epilogue ----
    bool active = (tid < ROWS_);
    int it = tid / 7;
    int jt = tid - it * 7;

    if (active) {
        float acc[49];
        #pragma unroll
        for (int k = 0; k < 49; k++) acc[k] = 0.0f;

        const float2* A  = (const float2*)(xs + it * 7 * STR_);
        const float2* Bm = (const float2*)(xs + (245 + jt * 7) * STR_);
        #pragma unroll 1
        for (int c2 = 0; c2 < 32; c2++) {
            float2 a[7], bb[7];
            #pragma unroll
            for (int k = 0; k < 7; k++) a[k]  = A[k * (STR_ / 2) + c2];
            #pragma unroll
            for (int k = 0; k < 7; k++) bb[k] = Bm[k * (STR_ / 2) + c2];
            #pragma unroll
            for (int ii = 0; ii < 7; ii++)
                #pragma unroll
                for (int jj = 0; jj < 7; jj++) {
                    acc[ii * 7 + jj] = fmaf(a[ii].x, bb[jj].x, acc[ii * 7 + jj]);
                    acc[ii * 7 + jj] = fmaf(a[ii].y, bb[jj].y, acc[ii * 7 + jj]);
                }
        }

        float qsq[7];
        int jbase = jt * 7;
        #pragma unroll
        for (int jj = 0; jj < 7; jj++) qsq[jj] = rsq[245 + jbase + jj];
        #pragma unroll
        for (int ii = 0; ii < 7; ii++) {
            float ri = rsq[it * 7 + ii];
            #pragma unroll
            for (int jj = 0; jj < 7; jj++) {
                float d2 = ri + qsq[jj] - 2.0f * acc[ii * 7 + jj];
                acc[ii * 7 + jj] = multi_gauss(d2);
            }
        }

        if (it < 35) {
            int s = it / 7;
            int i0 = it * 7 - s * 49;
            const float* gs = gam + s * 49 + jbase;
            const float* bs = bet + s * 49 + i0;
            float partial = 0.0f;
            #pragma unroll
            for (int ii = 0; ii < 7; ii++) {
                float rowsum = 0.0f;
                #pragma unroll
                for (int jj = 0; jj < 7; jj++) rowsum = fmaf(acc[ii * 7 + jj], gs[jj], rowsum);
                partial = fmaf(bs[ii], rowsum, partial);
            }
            scr[tid] = partial;
        } else {
            int q0 = it * 7 - 245;
            int qt = tid - 245;
            #pragma unroll
            for (int s = 0; s < 5; s++) {
                const float* gs = gam + s * 49;
                float pq = 0.0f;
                #pragma unroll
                for (int ii = 0; ii < 7; ii++) {
                    float rowsum = 0.0f;
                    #pragma unroll
                    for (int jj = 0; jj < 7; jj++) rowsum = fmaf(acc[ii * 7 + jj], gs[jbase + jj], rowsum);
                    pq = fmaf(gs[q0 + ii], rowsum, pq);
                }
                scrq[s * 49 + qt] = pq;
            }
        }
    }
    __syncthreads();

    if (tid < 10) {
        int s = tid % 5;
        const float* src = (tid < 5) ? (scr + s * 49) : (scrq + s * 49);
        float acc2 = 0.f;
        #pragma unroll
        for (int k = 0; k < 49; k++) acc2 += src[k];
        red[tid] = acc2;
    }
    __syncthreads();

    if (tid < NS_) {
        float p1 = red[12 + 2 * tid] + red[13 + 2 * tid];
        int idx = (bv * NS_ + tid) * NG_ + g;
        g_ps[idx] = p1 + red[5 + tid] - 2.0f * red[tid];
    }
}

// ---------------------------------------------------------------------------
// k3: out[b,v,s] = mean_g g_ps
// ---------------------------------------------------------------------------
__global__ void k3_reduce(float* __restrict__ out) {
    int o = blockIdx.x * blockDim.x + threadIdx.x;
    if (o < B_ * NQ_ * NS_) {
        float s = 0.0f;
        #pragma unroll
        for (int g = 0; g < NG_; g++) s += g_ps[o * NG_ + g];
        out[o] = 0.25f * s;
    }
}

extern "C" void kernel_launch(void* const* d_in, const int* in_sizes, int n_in,
                              void* d_out, int out_size) {
    const float* sup   = (const float*)d_in[0];  // (8,5,4,49,64)
    const float* qry   = (const float*)d_in[1];  // (8,75,4,49,64)
    const float* beta  = (const float*)d_in[2];  // (8,75,5,4,49)
    const float* gamma = (const float*)d_in[3];  // (8,75,5,4,49)
    float* out = (float*)d_out;                  // (8,75,5)

    const int smem2 = (ROWS_ * STR_ + 296 + 245 * 4 + 24) * (int)sizeof(float);
    static bool configured = false;
    if (!configured) {
        cudaFuncSetAttribute(k2_main, cudaFuncAttributeMaxDynamicSharedMemorySize, smem2);
        configured = true;
    }

    k1a_kss<<<B_ * NS_ * NG_, 64>>>(sup);
    k2_main<<<B_ * NQ_ * NG_, NT2_, smem2>>>(sup, qry, beta, gamma);
    k3_reduce<<<(B_ * NQ_ * NS_ + 255) / 256, 256>>>(out);
}

// round 8
// speedup vs baseline: 1.0857x; 1.0507x over previous
#include <cuda_runtime.h>
#include <cstdio>
#include <cstdint>

#define B_   8
#define NQ_  75
#define NS_  5
#define NG_  4
#define NF_  49
#define C_   64

#define ROWS_ 294
#define STR_  68
#define NT2_  320

__device__ float g_p1[B_ * NQ_ * NS_ * NG_];
__device__ float g_p2[B_ * NQ_ * NS_ * NG_];
__device__ float g_kss[B_ * NS_ * NG_ * NF_ * NF_];

__device__ __forceinline__ float multi_gauss(float d2) {
    d2 = fmaxf(d2, 0.0f);
    float t  = __expf(-0.125f * d2);
    float t2 = t * t;
    float t4 = t2 * t2;
    float t8 = t4 * t4;
    float t16 = t8 * t8;
    return t + t2 + t4 + t8 + t16;
}

// ---------------------------------------------------------------------------
// k1a: per (b,s,g) -> Kss (49x49) -> g_kss
// ---------------------------------------------------------------------------
__global__ __launch_bounds__(64) void k1a_kss(const float* __restrict__ sup) {
    __shared__ float sraw[49 * STR_];
    __shared__ float ssq[52];

    int bid = blockIdx.x;
    int tid = threadIdx.x;

    const float* sb = sup + (size_t)bid * 49 * 64;
    for (int idx = tid; idx < 49 * 16; idx += 64) {
        int r = idx >> 4, c4 = idx & 15;
        *(float4*)(sraw + r * STR_ + c4 * 4) = *(const float4*)(sb + r * 64 + c4 * 4);
    }
    __syncthreads();

    if (tid < 49) {
        const float2* xr = (const float2*)(sraw + tid * STR_);
        float a0 = 0.f, a1 = 0.f;
        #pragma unroll
        for (int c = 0; c < 32; c++) { float2 x = xr[c]; a0 = fmaf(x.x, x.x, a0); a1 = fmaf(x.y, x.y, a1); }
        ssq[tid] = a0 + a1;
    }
    __syncthreads();

    if (tid < 49) {
        int it = tid / 7, jt = tid - it * 7;
        float acc[49];
        #pragma unroll
        for (int k = 0; k < 49; k++) acc[k] = 0.f;
        const float2* A  = (const float2*)(sraw + it * 7 * STR_);
        const float2* Bm = (const float2*)(sraw + jt * 7 * STR_);
        #pragma unroll 1
        for (int c2 = 0; c2 < 32; c2++) {
            float2 a[7], bb[7];
            #pragma unroll
            for (int k = 0; k < 7; k++) a[k]  = A[k * (STR_ / 2) + c2];
            #pragma unroll
            for (int k = 0; k < 7; k++) bb[k] = Bm[k * (STR_ / 2) + c2];
            #pragma unroll
            for (int ii = 0; ii < 7; ii++)
                #pragma unroll
                for (int jj = 0; jj < 7; jj++) {
                    acc[ii * 7 + jj] = fmaf(a[ii].x, bb[jj].x, acc[ii * 7 + jj]);
                    acc[ii * 7 + jj] = fmaf(a[ii].y, bb[jj].y, acc[ii * 7 + jj]);
                }
        }
        float* kout = g_kss + (size_t)bid * 2401;
        #pragma unroll
        for (int ii = 0; ii < 7; ii++) {
            float ri = ssq[it * 7 + ii];
            #pragma unroll
            for (int jj = 0; jj < 7; jj++) {
                float d2 = ri + ssq[jt * 7 + jj] - 2.0f * acc[ii * 7 + jj];
                kout[(it * 7 + ii) * 49 + jt * 7 + jj] = multi_gauss(d2);
            }
        }
    }
}

// ---------------------------------------------------------------------------
// k1b: per (b,s,g,vchunk of 15) -> beta^T Kss beta
// ---------------------------------------------------------------------------
__global__ __launch_bounds__(256) void k1b_bilinear(const float* __restrict__ beta) {
    __shared__ float kss[49 * 50];
    __shared__ float betas[15 * 50];
    __shared__ float scr[735];

    int bid = blockIdx.x;
    int g = bid & 3;
    int rest = bid >> 2;
    int s = rest % NS_;  rest /= NS_;
    int vt = rest % 5;
    int b = rest / 5;
    int tid = threadIdx.x;

    int bid160 = (b * NS_ + s) * NG_ + g;
    const float* ksrc = g_kss + (size_t)bid160 * 2401;
    for (int idx = tid; idx < 2401; idx += 256) {
        int i = idx / 49, j = idx - i * 49;
        kss[i * 50 + j] = ksrc[idx];
    }
    for (int idx = tid; idx < 15 * 49; idx += 256) {
        int vv = idx / 49, j = idx - vv * 49;
        int v = vt * 15 + vv;
        size_t off = ((size_t)((b * NQ_ + v) * NS_ + s) * NG_ + g) * 49 + j;
        betas[vv * 50 + j] = beta[off];
    }
    __syncthreads();

    for (int t = tid; t < 735; t += 256) {
        int vv = t / 49, i = t - vv * 49;
        const float2* kr = (const float2*)(kss + i * 50);
        const float2* bv = (const float2*)(betas + vv * 50);
        float r0 = 0.f, r1 = 0.f;
        #pragma unroll
        for (int c = 0; c < 24; c++) {
            float2 kk = kr[c], bb = bv[c];
            r0 = fmaf(kk.x, bb.x, r0);
            r1 = fmaf(kk.y, bb.y, r1);
        }
        float r = r0 + r1 + kss[i * 50 + 48] * betas[vv * 50 + 48];
        scr[t] = betas[vv * 50 + i] * r;
    }
    __syncthreads();

    if (tid < 15) {
        float acc = 0.f;
        #pragma unroll
        for (int k = 0; k < 49; k++) acc += scr[tid * 49 + k];
        int v = vt * 15 + tid;
        g_p1[((b * NQ_ + v) * NS_ + s) * NG_ + g] = acc;
    }
}

// ---------------------------------------------------------------------------
// k2: per (b,v,g). Dots via 7x7 scalar-FFMA micro-tiles, fused epilogue.
// Single-pass load with in-warp rsq reduce. Writes mmd_q - 2*mmd_sq.
// ---------------------------------------------------------------------------
__global__ __launch_bounds__(NT2_, 2) void k2_main(const float* __restrict__ sup,
                                                   const float* __restrict__ qry,
                                                   const float* __restrict__ beta,
                                                   const float* __restrict__ gamma) {
    extern __shared__ float sm[];
    float* xs   = sm;                     // 294*68
    float* rsq  = xs + ROWS_ * STR_;      // 296
    float* bet  = rsq + 296;              // 245
    float* gam  = bet + 245;              // 245
    float* scr  = gam + 245;              // 245
    float* scrq = scr + 245;              // 245
    float* red  = scrq + 245;             // 16

    int bid = blockIdx.x;
    int g = bid & 3;
    int bv = bid >> 2;
    int b = bv / NQ_;
    int tid = threadIdx.x;

    const float* supb = sup + (size_t)(b * (NS_ * NG_) + g) * 49 * 64;
    const float* qryb = qry + ((size_t)bv * NG_ + g) * 49 * 64;

    #pragma unroll 1
    for (int pass = 0; pass < 15; pass++) {
        int idx = tid + pass * NT2_;
        float sq = 0.f;
        int r = idx >> 4, c4 = idx & 15;
        bool ok = (idx < ROWS_ * 16);
        if (ok) {
            float4 v;
            if (r < 245) {
                int s = r / 49;
                int i = r - s * 49;
                v = *(const float4*)(supb + (size_t)s * (NG_ * 49 * 64) + i * 64 + c4 * 4);
            } else {
                v = *(const float4*)(qryb + (r - 245) * 64 + c4 * 4);
            }
            *(float4*)(xs + r * STR_ + c4 * 4) = v;
            sq = fmaf(v.x, v.x, fmaf(v.y, v.y, fmaf(v.z, v.z, v.w * v.w)));
        }
        #pragma unroll
        for (int o = 1; o < 16; o <<= 1) sq += __shfl_xor_sync(0xffffffffu, sq, o);
        if (ok && c4 == 0) rsq[r] = sq;
    }
    for (int idx = tid; idx < NS_ * 49; idx += NT2_) {
        int s = idx / 49, j = idx - s * 49;
        size_t off = ((size_t)(bv * NS_ + s) * NG_ + g) * 49 + j;
        bet[idx] = beta[off];
        gam[idx] = gamma[off];
    }
    __syncthreads();

    bool active = (tid < ROWS_);
    int it = tid / 7;
    int jt = tid - it * 7;

    if (active) {
        float acc[49];
        #pragma unroll
        for (int k = 0; k < 49; k++) acc[k] = 0.0f;

        const float2* A  = (const float2*)(xs + it * 7 * STR_);
        const float2* Bm = (const float2*)(xs + (245 + jt * 7) * STR_);
        #pragma unroll 1
        for (int c2 = 0; c2 < 32; c2++) {
            float2 a[7], bb[7];
            #pragma unroll
            for (int k = 0; k < 7; k++) a[k]  = A[k * (STR_ / 2) + c2];
            #pragma unroll
            for (int k = 0; k < 7; k++) bb[k] = Bm[k * (STR_ / 2) + c2];
            #pragma unroll
            for (int ii = 0; ii < 7; ii++)
                #pragma unroll
                for (int jj = 0; jj < 7; jj++) {
                    acc[ii * 7 + jj] = fmaf(a[ii].x, bb[jj].x, acc[ii * 7 + jj]);
                    acc[ii * 7 + jj] = fmaf(a[ii].y, bb[jj].y, acc[ii * 7 + jj]);
                }
        }

        float qsq[7];
        int jbase = jt * 7;
        #pragma unroll
        for (int jj = 0; jj < 7; jj++) qsq[jj] = rsq[245 + jbase + jj];
        #pragma unroll
        for (int ii = 0; ii < 7; ii++) {
            float ri = rsq[it * 7 + ii];
            #pragma unroll
            for (int jj = 0; jj < 7; jj++) {
                float d2 = ri + qsq[jj] - 2.0f * acc[ii * 7 + jj];
                acc[ii * 7 + jj] = multi_gauss(d2);
            }
        }

        if (it < 35) {
            int s = it / 7;
            int i0 = it * 7 - s * 49;
            const float* gs = gam + s * 49 + jbase;
            const float* bs = bet + s * 49 + i0;
            float partial = 0.0f;
            #pragma unroll
            for (int ii = 0; ii < 7; ii++) {
                float rowsum = 0.0f;
                #pragma unroll
                for (int jj = 0; jj < 7; jj++) rowsum = fmaf(acc[ii * 7 + jj], gs[jj], rowsum);
                partial = fmaf(bs[ii], rowsum, partial);
            }
            scr[tid] = partial;
        } else {
            int q0 = it * 7 - 245;
            int qt = tid - 245;
            #pragma unroll
            for (int s = 0; s < 5; s++) {
                const float* gs = gam + s * 49;
                float pq = 0.0f;
                #pragma unroll
                for (int ii = 0; ii < 7; ii++) {
                    float rowsum = 0.0f;
                    #pragma unroll
                    for (int jj = 0; jj < 7; jj++) rowsum = fmaf(acc[ii * 7 + jj], gs[jbase + jj], rowsum);
                    pq = fmaf(gs[q0 + ii], rowsum, pq);
                }
                scrq[s * 49 + qt] = pq;
            }
        }
    }
    __syncthreads();

    if (tid < 10) {
        int s = tid % 5;
        const float* src = (tid < 5) ? (scr + s * 49) : (scrq + s * 49);
        float acc2 = 0.f;
        #pragma unroll
        for (int k = 0; k < 49; k++) acc2 += src[k];
        red[tid] = acc2;
    }
    __syncthreads();

    if (tid < NS_) {
        int idx = (bv * NS_ + tid) * NG_ + g;
        g_p2[idx] = red[5 + tid] - 2.0f * red[tid];
    }
}

__global__ void k3_reduce(float* __restrict__ out) {
    int o = blockIdx.x * blockDim.x + threadIdx.x;
    if (o < B_ * NQ_ * NS_) {
        float s = 0.0f;
        #pragma unroll
        for (int g = 0; g < NG_; g++) s += g_p1[o * NG_ + g] + g_p2[o * NG_ + g];
        out[o] = 0.25f * s;
    }
}

extern "C" void kernel_launch(void* const* d_in, const int* in_sizes, int n_in,
                              void* d_out, int out_size) {
    const float* sup   = (const float*)d_in[0];
    const float* qry   = (const float*)d_in[1];
    const float* beta  = (const float*)d_in[2];
    const float* gamma = (const float*)d_in[3];
    float* out = (float*)d_out;

    const int smem2 = (ROWS_ * STR_ + 296 + 245 * 4 + 16) * (int)sizeof(float);

    // One-time setup on the first (uncaptured) correctness call; reused during capture.
    static cudaStream_t s2 = nullptr;
    static cudaEvent_t evA = nullptr, evB = nullptr;
    static bool configured = false;
    if (!configured) {
        cudaFuncSetAttribute(k2_main, cudaFuncAttributeMaxDynamicSharedMemorySize, smem2);
        cudaStreamCreateWithFlags(&s2, cudaStreamNonBlocking);
        cudaEventCreateWithFlags(&evA, cudaEventDisableTiming);
        cudaEventCreateWithFlags(&evB, cudaEventDisableTiming);
        configured = true;
    }

    // Fork: k1a->k1b (mmd_s chain, latency-bound) runs concurrently with k2
    // (throughput-bound); join before k3.
    cudaEventRecord(evA, 0);
    cudaStreamWaitEvent(s2, evA, 0);
    k1a_kss<<<B_ * NS_ * NG_, 64, 0, s2>>>(sup);
    k1b_bilinear<<<B_ * NS_ * NG_ * 5, 256, 0, s2>>>(beta);
    cudaEventRecord(evB, s2);

    k2_main<<<B_ * NQ_ * NG_, NT2_, smem2>>>(sup, qry, beta, gamma);

    cudaStreamWaitEvent(0, evB, 0);
    k3_reduce<<<(B_ * NQ_ * NS_ + 255) / 256, 256>>>(out);
}

// round 9
// speedup vs baseline: 1.1648x; 1.0729x over previous
#include <cuda_runtime.h>
#include <cstdio>
#include <cstdint>

#define B_   8
#define NQ_  75
#define NS_  5
#define NG_  4
#define NF_  49
#define C_   64

#define ROWS_ 294
#define STR_  68
#define NT2_  320

__device__ float g_p1[B_ * NQ_ * NS_ * NG_];
__device__ float g_p2[B_ * NQ_ * NS_ * NG_];
__device__ float g_kss[B_ * NS_ * NG_ * NF_ * NF_];

__device__ __forceinline__ float multi_gauss(float d2) {
    d2 = fmaxf(d2, 0.0f);
    float t  = __expf(-0.125f * d2);
    float t2 = t * t;
    float t4 = t2 * t2;
    float t8 = t4 * t4;
    float t16 = t8 * t8;
    return t + t2 + t4 + t8 + t16;
}

// ---------------------------------------------------------------------------
// k1a: per (b,s,g) -> Kss (49x49) once -> g_kss
// ---------------------------------------------------------------------------
__global__ __launch_bounds__(64) void k1a_kss(const float* __restrict__ sup) {
    __shared__ float sraw[49 * STR_];
    __shared__ float ssq[52];

    int bid = blockIdx.x;
    int tid = threadIdx.x;

    const float* sb = sup + (size_t)bid * 49 * 64;
    for (int idx = tid; idx < 49 * 16; idx += 64) {
        int r = idx >> 4, c4 = idx & 15;
        *(float4*)(sraw + r * STR_ + c4 * 4) = *(const float4*)(sb + r * 64 + c4 * 4);
    }
    __syncthreads();

    if (tid < 49) {
        const float2* xr = (const float2*)(sraw + tid * STR_);
        float a0 = 0.f, a1 = 0.f;
        #pragma unroll
        for (int c = 0; c < 32; c++) { float2 x = xr[c]; a0 = fmaf(x.x, x.x, a0); a1 = fmaf(x.y, x.y, a1); }
        ssq[tid] = a0 + a1;
    }
    __syncthreads();

    if (tid < 49) {
        int it = tid / 7, jt = tid - it * 7;
        float acc[49];
        #pragma unroll
        for (int k = 0; k < 49; k++) acc[k] = 0.f;
        const float2* A  = (const float2*)(sraw + it * 7 * STR_);
        const float2* Bm = (const float2*)(sraw + jt * 7 * STR_);
        #pragma unroll 1
        for (int c2 = 0; c2 < 32; c2++) {
            float2 a[7], bb[7];
            #pragma unroll
            for (int k = 0; k < 7; k++) a[k]  = A[k * (STR_ / 2) + c2];
            #pragma unroll
            for (int k = 0; k < 7; k++) bb[k] = Bm[k * (STR_ / 2) + c2];
            #pragma unroll
            for (int ii = 0; ii < 7; ii++)
                #pragma unroll
                for (int jj = 0; jj < 7; jj++) {
                    acc[ii * 7 + jj] = fmaf(a[ii].x, bb[jj].x, acc[ii * 7 + jj]);
                    acc[ii * 7 + jj] = fmaf(a[ii].y, bb[jj].y, acc[ii * 7 + jj]);
                }
        }
        float* kout = g_kss + (size_t)bid * 2401;
        #pragma unroll
        for (int ii = 0; ii < 7; ii++) {
            float ri = ssq[it * 7 + ii];
            #pragma unroll
            for (int jj = 0; jj < 7; jj++) {
                float d2 = ri + ssq[jt * 7 + jj] - 2.0f * acc[ii * 7 + jj];
                kout[(it * 7 + ii) * 49 + jt * 7 + jj] = multi_gauss(d2);
            }
        }
    }
}

// ---------------------------------------------------------------------------
// k1b: per (b,s,g,vchunk of 15) -> beta^T Kss beta (Kss L2-hot)
// ---------------------------------------------------------------------------
__global__ __launch_bounds__(256) void k1b_bilinear(const float* __restrict__ beta) {
    __shared__ float kss[49 * 50];
    __shared__ float betas[15 * 50];
    __shared__ float scr[735];

    int bid = blockIdx.x;
    int g = bid & 3;
    int rest = bid >> 2;
    int s = rest % NS_;  rest /= NS_;
    int vt = rest % 5;
    int b = rest / 5;
    int tid = threadIdx.x;

    int bid160 = (b * NS_ + s) * NG_ + g;
    const float* ksrc = g_kss + (size_t)bid160 * 2401;
    for (int idx = tid; idx < 2401; idx += 256) {
        int i = idx / 49, j = idx - i * 49;
        kss[i * 50 + j] = ksrc[idx];
    }
    for (int idx = tid; idx < 15 * 49; idx += 256) {
        int vv = idx / 49, j = idx - vv * 49;
        int v = vt * 15 + vv;
        size_t off = ((size_t)((b * NQ_ + v) * NS_ + s) * NG_ + g) * 49 + j;
        betas[vv * 50 + j] = beta[off];
    }
    __syncthreads();

    for (int t = tid; t < 735; t += 256) {
        int vv = t / 49, i = t - vv * 49;
        const float2* kr = (const float2*)(kss + i * 50);
        const float2* bv = (const float2*)(betas + vv * 50);
        float r0 = 0.f, r1 = 0.f;
        #pragma unroll
        for (int c = 0; c < 24; c++) {
            float2 kk = kr[c], bb = bv[c];
            r0 = fmaf(kk.x, bb.x, r0);
            r1 = fmaf(kk.y, bb.y, r1);
        }
        float r = r0 + r1 + kss[i * 50 + 48] * betas[vv * 50 + 48];
        scr[t] = betas[vv * 50 + i] * r;
    }
    __syncthreads();

    if (tid < 15) {
        float acc = 0.f;
        #pragma unroll
        for (int k = 0; k < 49; k++) acc += scr[tid * 49 + k];
        int v = vt * 15 + tid;
        g_p1[((b * NQ_ + v) * NS_ + s) * NG_ + g] = acc;
    }
}

// ---------------------------------------------------------------------------
// k2: per (b,v,g). R4-exact: batched float4 load (high MLP), separate rsq
// pass, 7x7 scalar-FFMA micro-tiles, fused epilogue, scratch reduce.
// ---------------------------------------------------------------------------
__global__ __launch_bounds__(NT2_, 2) void k2_main(const float* __restrict__ sup,
                                                   const float* __restrict__ qry,
                                                   const float* __restrict__ beta,
                                                   const float* __restrict__ gamma) {
    extern __shared__ float sm[];
    float* xs   = sm;                     // 294*68
    float* rsq  = xs + ROWS_ * STR_;      // 296
    float* bet  = rsq + 296;              // 245
    float* gam  = bet + 245;              // 245
    float* scr  = gam + 245;              // 245
    float* scrq = scr + 245;              // 245
    float* red  = scrq + 245;             // 16

    int bid = blockIdx.x;
    int g = bid & 3;
    int bv = bid >> 2;
    int b = bv / NQ_;
    int tid = threadIdx.x;

    const float* supb = sup + (size_t)(b * (NS_ * NG_) + g) * 49 * 64;
    const float* qryb = qry + ((size_t)bv * NG_ + g) * 49 * 64;

    for (int idx = tid; idx < ROWS_ * 16; idx += NT2_) {
        int r = idx >> 4, c4 = idx & 15;
        float4 val;
        if (r < 245) {
            int s = r / 49;
            int i = r - s * 49;
            val = *(const float4*)(supb + (size_t)s * (NG_ * 49 * 64) + i * 64 + c4 * 4);
        } else {
            val = *(const float4*)(qryb + (r - 245) * 64 + c4 * 4);
        }
        *(float4*)(xs + r * STR_ + c4 * 4) = val;
    }
    for (int idx = tid; idx < NS_ * 49; idx += NT2_) {
        int s = idx / 49, j = idx - s * 49;
        size_t off = ((size_t)(bv * NS_ + s) * NG_ + g) * 49 + j;
        bet[idx] = beta[off];
        gam[idx] = gamma[off];
    }
    __syncthreads();

    for (int r = tid; r < ROWS_; r += NT2_) {
        const float2* xr = (const float2*)(xs + r * STR_);
        float a0 = 0.f, a1 = 0.f;
        #pragma unroll
        for (int c = 0; c < 32; c++) { float2 x = xr[c]; a0 = fmaf(x.x, x.x, a0); a1 = fmaf(x.y, x.y, a1); }
        rsq[r] = a0 + a1;
    }
    __syncthreads();

    bool active = (tid < ROWS_);
    int it = tid / 7;
    int jt = tid - it * 7;

    if (active) {
        float acc[49];
        #pragma unroll
        for (int k = 0; k < 49; k++) acc[k] = 0.0f;

        const float2* A  = (const float2*)(xs + it * 7 * STR_);
        const float2* Bm = (const float2*)(xs + (245 + jt * 7) * STR_);
        #pragma unroll 1
        for (int c2 = 0; c2 < 32; c2++) {
            float2 a[7], bb[7];
            #pragma unroll
            for (int k = 0; k < 7; k++) a[k]  = A[k * (STR_ / 2) + c2];
            #pragma unroll
            for (int k = 0; k < 7; k++) bb[k] = Bm[k * (STR_ / 2) + c2];
            #pragma unroll
            for (int ii = 0; ii < 7; ii++)
                #pragma unroll
                for (int jj = 0; jj < 7; jj++) {
                    acc[ii * 7 + jj] = fmaf(a[ii].x, bb[jj].x, acc[ii * 7 + jj]);
                    acc[ii * 7 + jj] = fmaf(a[ii].y, bb[jj].y, acc[ii * 7 + jj]);
                }
        }

        float qsq[7];
        int jbase = jt * 7;
        #pragma unroll
        for (int jj = 0; jj < 7; jj++) qsq[jj] = rsq[245 + jbase + jj];
        #pragma unroll
        for (int ii = 0; ii < 7; ii++) {
            float ri = rsq[it * 7 + ii];
            #pragma unroll
            for (int jj = 0; jj < 7; jj++) {
                float d2 = ri + qsq[jj] - 2.0f * acc[ii * 7 + jj];
                acc[ii * 7 + jj] = multi_gauss(d2);
            }
        }

        if (it < 35) {
            int s = it / 7;
            int i0 = it * 7 - s * 49;
            const float* gs = gam + s * 49 + jbase;
            const float* bs = bet + s * 49 + i0;
            float partial = 0.0f;
            #pragma unroll
            for (int ii = 0; ii < 7; ii++) {
                float rowsum = 0.0f;
                #pragma unroll
                for (int jj = 0; jj < 7; jj++) rowsum = fmaf(acc[ii * 7 + jj], gs[jj], rowsum);
                partial = fmaf(bs[ii], rowsum, partial);
            }
            scr[tid] = partial;
        } else {
            int q0 = it * 7 - 245;
            int qt = tid - 245;
            #pragma unroll
            for (int s = 0; s < 5; s++) {
                const float* gs = gam + s * 49;
                float pq = 0.0f;
                #pragma unroll
                for (int ii = 0; ii < 7; ii++) {
                    float rowsum = 0.0f;
                    #pragma unroll
                    for (int jj = 0; jj < 7; jj++) rowsum = fmaf(acc[ii * 7 + jj], gs[jbase + jj], rowsum);
                    pq = fmaf(gs[q0 + ii], rowsum, pq);
                }
                scrq[s * 49 + qt] = pq;
            }
        }
    }
    __syncthreads();

    if (tid < 10) {
        int s = tid % 5;
        const float* src = (tid < 5) ? (scr + s * 49) : (scrq + s * 49);
        float acc2 = 0.f;
        #pragma unroll
        for (int k = 0; k < 49; k++) acc2 += src[k];
        red[tid] = acc2;
    }
    __syncthreads();

    if (tid < NS_) {
        int idx = (bv * NS_ + tid) * NG_ + g;
        g_p2[idx] = red[5 + tid] - 2.0f * red[tid];
    }
}

__global__ void k3_reduce(float* __restrict__ out) {
    int o = blockIdx.x * blockDim.x + threadIdx.x;
    if (o < B_ * NQ_ * NS_) {
        float s = 0.0f;
        #pragma unroll
        for (int g = 0; g < NG_; g++) s += g_p1[o * NG_ + g] + g_p2[o * NG_ + g];
        out[o] = 0.25f * s;
    }
}

extern "C" void kernel_launch(void* const* d_in, const int* in_sizes, int n_in,
                              void* d_out, int out_size) {
    const float* sup   = (const float*)d_in[0];
    const float* qry   = (const float*)d_in[1];
    const float* beta  = (const float*)d_in[2];
    const float* gamma = (const float*)d_in[3];
    float* out = (float*)d_out;

    const int smem2 = (ROWS_ * STR_ + 296 + 245 * 4 + 16) * (int)sizeof(float);

    static cudaStream_t s2 = nullptr;
    static cudaEvent_t evA = nullptr, evB = nullptr;
    static bool configured = false;
    if (!configured) {
        cudaFuncSetAttribute(k2_main, cudaFuncAttributeMaxDynamicSharedMemorySize, smem2);
        cudaStreamCreateWithFlags(&s2, cudaStreamNonBlocking);
        cudaEventCreateWithFlags(&evA, cudaEventDisableTiming);
        cudaEventCreateWithFlags(&evB, cudaEventDisableTiming);
        configured = true;
    }

    // Fork: latency-bound k1a->k1b runs concurrently with throughput-bound k2.
    cudaEventRecord(evA, 0);
    cudaStreamWaitEvent(s2, evA, 0);
    k1a_kss<<<B_ * NS_ * NG_, 64, 0, s2>>>(sup);
    k1b_bilinear<<<B_ * NS_ * NG_ * 5, 256, 0, s2>>>(beta);
    cudaEventRecord(evB, s2);

    k2_main<<<B_ * NQ_ * NG_, NT2_, smem2>>>(sup, qry, beta, gamma);

    cudaStreamWaitEvent(0, evB, 0);
    k3_reduce<<<(B_ * NQ_ * NS_ + 255) / 256, 256>>>(out);
}